// round 2
// baseline (speedup 1.0000x reference)
#include <cuda_runtime.h>
#include <math.h>

// ---------------- problem constants ----------------
#define B_    4
#define NQ_   1024
#define NKV_  2048
#define H_    8
#define D_    288     // per-head feature dim: 16 mv-ch * 16 blades + 32 scalars
#define DP_   292     // padded smem stride (float4-aligned)
#define TQ_   32
#define TK_   32

__device__ constexpr int   GRADEA[16] = {0,1,1,1,1,2,2,2,2,2,2,3,3,3,3,4};
__device__ constexpr float METRICA[16] = {1.f,1.f,-1.f,-1.f,-1.f,-1.f,-1.f,-1.f,
                                          1.f,1.f, 1.f, 1.f, 1.f, 1.f,-1.f,-1.f};
__constant__ int GRADE_RT[16] = {0,1,1,1,1,2,2,2,2,2,2,3,3,3,3,4};

// ---------------- scratch (device globals; no cudaMalloc allowed) ----------------
// Q: [B][H][NQ][288], K/V: [B][H][NKV][288], O: [B][NQ][H][288]
__device__ float QB[(size_t)B_*H_*NQ_*D_];
__device__ float KB[(size_t)B_*H_*NKV_*D_];
__device__ float VB[(size_t)B_*H_*NKV_*D_];
__device__ float OB[(size_t)B_*NQ_*H_*D_];

// ============================================================================
// QKV projection: equi_linear for one token per block (128 threads).
// x_mv: [tok][16][16], x_s: [tok][32]
// w_mv: [128][16][5], w_s2mv: [128][32], w_mvs2s: [256][16], w_s2s: [256][32]
// Output written head-split: out[(b*8+head)*ntok + n][feat], feat = hid*16+x (mv), 256+hid (s)
// dst: 0=QB, 1=KB, 2=VB.  applyMetric multiplies mv features by METRIC[x] (K only).
// ============================================================================
__global__ void proj_kernel(const float* __restrict__ x_mv, const float* __restrict__ x_s,
                            const float* __restrict__ w_mv, const float* __restrict__ w_s2mv,
                            const float* __restrict__ w_mvs2s, const float* __restrict__ w_s2s,
                            const float* __restrict__ b_mv, const float* __restrict__ b_s,
                            int ntok, int dst, int applyMetric)
{
    __shared__ float xmv[256];
    __shared__ float xs[32];
    const int t   = blockIdx.x;
    const int b   = t / ntok;
    const int n   = t % ntok;
    const int tid = threadIdx.x;   // 128 threads

    const float* xp = x_mv + (size_t)t * 256;
    xmv[tid]       = xp[tid];
    xmv[tid + 128] = xp[tid + 128];
    if (tid < 32) xs[tid] = x_s[(size_t)t * 32 + tid];
    __syncthreads();

    float* out = (dst == 0) ? QB : (dst == 1) ? KB : VB;

    // ---- multivector output channel o = tid (0..127) ----
    {
        const int o = tid;
        const float* wr = w_mv + o * 80;   // [16][5]
        float y[16];
#pragma unroll
        for (int x = 0; x < 16; ++x) {
            float acc = 0.f;
#pragma unroll
            for (int i = 0; i < 16; ++i)
                acc += xmv[i * 16 + x] * wr[i * 5 + GRADEA[x]];
            y[x] = acc;
        }
        // scalar -> mv (blade 0) + bias
        float a0 = b_mv[o];
        const float* ws = w_s2mv + o * 32;
#pragma unroll
        for (int s = 0; s < 32; ++s) a0 += xs[s] * ws[s];
        y[0] += a0;

        const int head = o & 7, hid = o >> 3;
        float* op = out + ((size_t)(b * 8 + head) * ntok + n) * D_ + hid * 16;
        if (applyMetric) {
#pragma unroll
            for (int x = 0; x < 16; ++x) op[x] = y[x] * METRICA[x];
        } else {
#pragma unroll
            for (int x = 0; x < 16; ++x) op[x] = y[x];
        }
    }

    // ---- scalar outputs o = 2*tid, 2*tid+1 (0..255) ----
#pragma unroll
    for (int r = 0; r < 2; ++r) {
        const int o = tid * 2 + r;
        float y = b_s[o];
        const float* wm = w_mvs2s + o * 16;
#pragma unroll
        for (int i = 0; i < 16; ++i) y += xmv[i * 16] * wm[i];
        const float* ws = w_s2s + o * 32;
#pragma unroll
        for (int s = 0; s < 32; ++s) y += xs[s] * ws[s];
        const int head = o & 7, hid = o >> 3;
        out[((size_t)(b * 8 + head) * ntok + n) * D_ + 256 + hid] = y;
    }
}

// ============================================================================
// Flash attention (fp32, online softmax).
// grid = (NQ/TQ, B*H), block = 256.
// Thread (ty=tid/16, tx=tid%15) computes scores for queries {ty, ty+16} x keys
// {tx, tx+16}; AV phase: same 2 queries, dim slice {tx + 16*j, j<18}, acc in regs.
// ============================================================================
__global__ void attn_kernel()
{
    extern __shared__ float sm[];
    float* Qs  = sm;                    // TQ*DP
    float* Ks  = Qs + TQ_ * DP_;        // TK*DP
    float* Vs  = Ks + TK_ * DP_;        // TK*DP
    float* Ps  = Vs + TK_ * DP_;        // TQ*TK
    float* msm = Ps + TQ_ * TK_;        // TQ
    float* lsm = msm + TQ_;             // TQ

    const int qt  = blockIdx.x;
    const int bh  = blockIdx.y;
    const int tid = threadIdx.x;

    const float* Qp = QB + ((size_t)bh * NQ_ + qt * TQ_) * D_;
    const float* Kp = KB + (size_t)bh * NKV_ * D_;
    const float* Vp = VB + (size_t)bh * NKV_ * D_;

    for (int idx = tid; idx < TQ_ * D_; idx += 256) {
        int q = idx / D_, d = idx % D_;
        Qs[q * DP_ + d] = Qp[idx];
    }
    if (tid < TQ_) { msm[tid] = -1e30f; lsm[tid] = 0.f; }

    const int ty = tid >> 4, tx = tid & 15;
    const int q0 = ty, q1 = ty + 16;

    float acc0[18], acc1[18];
#pragma unroll
    for (int j = 0; j < 18; ++j) { acc0[j] = 0.f; acc1[j] = 0.f; }
    __syncthreads();

    const float SCALE = 0.0589255650988789f;  // 1/sqrt(288)

    for (int kt = 0; kt < NKV_ / TK_; ++kt) {
        const float* kp = Kp + (size_t)kt * TK_ * D_;
        const float* vp = Vp + (size_t)kt * TK_ * D_;
        for (int idx = tid; idx < TK_ * D_; idx += 256) {
            int r = idx / D_, d = idx % D_;
            Ks[r * DP_ + d] = kp[idx];
            Vs[r * DP_ + d] = vp[idx];
        }
        __syncthreads();

        // ---- scores: 2x2 micro-tile ----
        float s00 = 0.f, s01 = 0.f, s10 = 0.f, s11 = 0.f;
        const float4* qa = (const float4*)(Qs + q0 * DP_);
        const float4* qb = (const float4*)(Qs + q1 * DP_);
        const float4* ka = (const float4*)(Ks + tx * DP_);
        const float4* kb = (const float4*)(Ks + (tx + 16) * DP_);
#pragma unroll 8
        for (int d4 = 0; d4 < D_ / 4; ++d4) {
            float4 A = qa[d4], Bv = qb[d4], C = ka[d4], Dv = kb[d4];
            s00 += A.x*C.x + A.y*C.y + A.z*C.z + A.w*C.w;
            s01 += A.x*Dv.x + A.y*Dv.y + A.z*Dv.z + A.w*Dv.w;
            s10 += Bv.x*C.x + Bv.y*C.y + Bv.z*C.z + Bv.w*C.w;
            s11 += Bv.x*Dv.x + Bv.y*Dv.y + Bv.z*Dv.z + Bv.w*Dv.w;
        }
        s00 *= SCALE; s01 *= SCALE; s10 *= SCALE; s11 *= SCALE;

        // ---- online softmax ----
        float t0 = fmaxf(s00, s01), t1 = fmaxf(s10, s11);
#pragma unroll
        for (int off = 8; off; off >>= 1) {
            t0 = fmaxf(t0, __shfl_xor_sync(0xffffffffu, t0, off, 16));
            t1 = fmaxf(t1, __shfl_xor_sync(0xffffffffu, t1, off, 16));
        }
        const float mo0 = msm[q0], mo1 = msm[q1];
        const float mn0 = fmaxf(mo0, t0), mn1 = fmaxf(mo1, t1);
        const float al0 = __expf(mo0 - mn0), al1 = __expf(mo1 - mn1);
        const float p00 = __expf(s00 - mn0), p01 = __expf(s01 - mn0);
        const float p10 = __expf(s10 - mn1), p11 = __expf(s11 - mn1);
        Ps[q0 * TK_ + tx]      = p00;
        Ps[q0 * TK_ + tx + 16] = p01;
        Ps[q1 * TK_ + tx]      = p10;
        Ps[q1 * TK_ + tx + 16] = p11;
        float r0 = p00 + p01, r1 = p10 + p11;
#pragma unroll
        for (int off = 8; off; off >>= 1) {
            r0 += __shfl_xor_sync(0xffffffffu, r0, off, 16);
            r1 += __shfl_xor_sync(0xffffffffu, r1, off, 16);
        }
        __syncwarp();
        if (tx == 0) {
            lsm[q0] = lsm[q0] * al0 + r0; msm[q0] = mn0;
            lsm[q1] = lsm[q1] * al1 + r1; msm[q1] = mn1;
        }
        __syncthreads();

        // ---- AV accumulation (acc in registers) ----
#pragma unroll
        for (int j = 0; j < 18; ++j) { acc0[j] *= al0; acc1[j] *= al1; }
        for (int ki = 0; ki < TK_; ++ki) {
            const float pv0 = Ps[q0 * TK_ + ki];
            const float pv1 = Ps[q1 * TK_ + ki];
            const float* vr = Vs + ki * DP_ + tx;
#pragma unroll
            for (int j = 0; j < 18; ++j) {
                float v = vr[16 * j];
                acc0[j] += pv0 * v;
                acc1[j] += pv1 * v;
            }
        }
        __syncthreads();
    }

    const float inv0 = 1.0f / lsm[q0];
    const float inv1 = 1.0f / lsm[q1];
    const int b = bh >> 3, h = bh & 7;
    const size_t base0 = (((size_t)(b * NQ_ + qt * TQ_ + q0)) * 8 + h) * D_;
    const size_t base1 = (((size_t)(b * NQ_ + qt * TQ_ + q1)) * 8 + h) * D_;
#pragma unroll
    for (int j = 0; j < 18; ++j) {
        OB[base0 + tx + 16 * j] = acc0[j] * inv0;
        OB[base1 + tx + 16 * j] = acc1[j] * inv1;
    }
}

// ============================================================================
// Output projection. One token per block (256 threads). Reads OB, writes d_out:
// [out_mv (4,1024,16,16)] then [out_s (4,1024,32)], concatenated.
// Recombine mapping: mv channel c = head*16 + hid, scalar c = head*32 + hid.
// ============================================================================
__global__ void outproj_kernel(const float* __restrict__ wo_mv, const float* __restrict__ wo_s2mv,
                               const float* __restrict__ wo_mvs2s, const float* __restrict__ wo_s2s,
                               const float* __restrict__ bo_mv, const float* __restrict__ bo_s,
                               float* __restrict__ d_out)
{
    __shared__ float xm[2048];   // [c=128][x=16]
    __shared__ float xsc[256];
    const int t   = blockIdx.x;
    const int tid = threadIdx.x;  // 256
    const float* ob = OB + (size_t)t * 8 * D_;

    for (int idx = tid; idx < 2048; idx += 256) {
        const int c = idx >> 4, x = idx & 15;
        const int head = c >> 4, hid = c & 15;
        xm[idx] = ob[head * D_ + hid * 16 + x];
    }
    {
        const int head = tid >> 5, hid = tid & 31;
        xsc[tid] = ob[head * D_ + 256 + hid];
    }
    __syncthreads();

    // out_mv: o = tid/16, x = tid%16
    {
        const int o = tid >> 4, x = tid & 15;
        const int g = GRADE_RT[x];
        const float* w = wo_mv + (size_t)o * 128 * 5 + g;
        float y = 0.f;
#pragma unroll 8
        for (int i = 0; i < 128; ++i) y += xm[i * 16 + x] * w[i * 5];
        if (x == 0) {
            float a = bo_mv[o];
            const float* ws = wo_s2mv + o * 256;
#pragma unroll 8
            for (int s = 0; s < 256; ++s) a += xsc[s] * ws[s];
            y += a;
        }
        d_out[(size_t)t * 256 + o * 16 + x] = y;
    }
    // out_s: threads 0..31
    if (tid < 32) {
        const int o = tid;
        float y = bo_s[o];
        const float* wm = wo_mvs2s + o * 128;
#pragma unroll 8
        for (int i = 0; i < 128; ++i) y += xm[i * 16] * wm[i];
        const float* ws = wo_s2s + o * 256;
#pragma unroll 8
        for (int s = 0; s < 256; ++s) y += xsc[s] * ws[s];
        d_out[(size_t)B_ * NQ_ * 256 + (size_t)t * 32 + o] = y;
    }
}

// ============================================================================
// Host entry
// ============================================================================
extern "C" void kernel_launch(void* const* d_in, const int* in_sizes, int n_in,
                              void* d_out, int out_size)
{
    (void)in_sizes; (void)n_in; (void)out_size;

    const float* mv_kv = (const float*)d_in[0];
    const float* mv_q  = (const float*)d_in[1];
    const float* s_kv  = (const float*)d_in[2];
    const float* s_q   = (const float*)d_in[3];

    const float** W = (const float**)(d_in + 4);  // 6 per group: q, k, v, o
    const float* wq_mv = (const float*)d_in[4],  *wq_s2mv = (const float*)d_in[5];
    const float* wq_m2s = (const float*)d_in[6], *wq_s2s = (const float*)d_in[7];
    const float* bq_mv = (const float*)d_in[8],  *bq_s = (const float*)d_in[9];
    const float* wk_mv = (const float*)d_in[10], *wk_s2mv = (const float*)d_in[11];
    const float* wk_m2s = (const float*)d_in[12],*wk_s2s = (const float*)d_in[13];
    const float* bk_mv = (const float*)d_in[14], *bk_s = (const float*)d_in[15];
    const float* wv_mv = (const float*)d_in[16], *wv_s2mv = (const float*)d_in[17];
    const float* wv_m2s = (const float*)d_in[18],*wv_s2s = (const float*)d_in[19];
    const float* bv_mv = (const float*)d_in[20], *bv_s = (const float*)d_in[21];
    const float* wo_mv = (const float*)d_in[22], *wo_s2mv = (const float*)d_in[23];
    const float* wo_m2s = (const float*)d_in[24],*wo_s2s = (const float*)d_in[25];
    const float* bo_mv = (const float*)d_in[26], *bo_s = (const float*)d_in[27];
    (void)W;

    const size_t attn_smem = (size_t)(TQ_ * DP_ + 2 * TK_ * DP_ + TQ_ * TK_ + 2 * TQ_) * sizeof(float);
    cudaFuncSetAttribute(attn_kernel, cudaFuncAttributeMaxDynamicSharedMemorySize, (int)attn_smem);

    proj_kernel<<<B_ * NQ_, 128>>>(mv_q, s_q, wq_mv, wq_s2mv, wq_m2s, wq_s2s, bq_mv, bq_s,
                                   NQ_, 0, 0);
    proj_kernel<<<B_ * NKV_, 128>>>(mv_kv, s_kv, wk_mv, wk_s2mv, wk_m2s, wk_s2s, bk_mv, bk_s,
                                    NKV_, 1, 1);
    proj_kernel<<<B_ * NKV_, 128>>>(mv_kv, s_kv, wv_mv, wv_s2mv, wv_m2s, wv_s2s, bv_mv, bv_s,
                                    NKV_, 2, 0);

    attn_kernel<<<dim3(NQ_ / TQ_, B_ * H_), 256, attn_smem>>>();

    outproj_kernel<<<B_ * NQ_, 256>>>(wo_mv, wo_s2mv, wo_m2s, wo_s2s, bo_mv, bo_s,
                                      (float*)d_out);
}

// round 3
// speedup vs baseline: 2.2995x; 2.2995x over previous
#include <cuda_runtime.h>
#include <math.h>
#include <stdint.h>

#define B_    4
#define NQ_   1024
#define NKV_  2048
#define D_    288

__device__ constexpr int   GRADEA[16] = {0,1,1,1,1,2,2,2,2,2,2,3,3,3,3,4};
__device__ constexpr float METRICA[16] = {1.f,1.f,-1.f,-1.f,-1.f,-1.f,-1.f,-1.f,
                                          1.f,1.f, 1.f, 1.f, 1.f, 1.f,-1.f,-1.f};
__constant__ int GRADE_RT[16] = {0,1,1,1,1,2,2,2,2,2,2,3,3,3,3,4};

__device__ float QB[(size_t)B_*8*NQ_*D_];
__device__ float KB[(size_t)B_*8*NKV_*D_];
__device__ float VB[(size_t)B_*8*NKV_*D_];
__device__ float VT[(size_t)B_*8*D_*NKV_];
__device__ float OB[(size_t)B_*NQ_*8*D_];

__device__ __forceinline__ float tf32f(float x) {
    uint32_t r; asm("cvt.rna.tf32.f32 %0,%1;" : "=r"(r) : "f"(x));
    return __uint_as_float(r);
}
#define MMA(c,a0,a1,a2,a3,b0,b1) \
    asm volatile("mma.sync.aligned.m16n8k8.row.col.f32.tf32.tf32.f32 " \
        "{%0,%1,%2,%3},{%4,%5,%6,%7},{%8,%9},{%0,%1,%2,%3};" \
        : "+f"((c)[0]),"+f"((c)[1]),"+f"((c)[2]),"+f"((c)[3]) \
        : "r"(a0),"r"(a1),"r"(a2),"r"(a3),"r"(b0),"r"(b1))

// ============================================================================
// QKV projection (one token per block, 128 threads) — unchanged from R0.
// ============================================================================
__global__ void proj_kernel(const float* __restrict__ x_mv, const float* __restrict__ x_s,
                            const float* __restrict__ w_mv, const float* __restrict__ w_s2mv,
                            const float* __restrict__ w_mvs2s, const float* __restrict__ w_s2s,
                            const float* __restrict__ b_mv, const float* __restrict__ b_s,
                            int ntok, int dst, int applyMetric)
{
    __shared__ float xmv[256];
    __shared__ float xs[32];
    const int t = blockIdx.x, b = t / ntok, n = t % ntok, tid = threadIdx.x;

    const float* xp = x_mv + (size_t)t * 256;
    xmv[tid] = xp[tid]; xmv[tid + 128] = xp[tid + 128];
    if (tid < 32) xs[tid] = x_s[(size_t)t * 32 + tid];
    __syncthreads();

    float* out = (dst == 0) ? QB : (dst == 1) ? KB : VB;
    {
        const int o = tid;
        const float* wr = w_mv + o * 80;
        float y[16];
#pragma unroll
        for (int x = 0; x < 16; ++x) {
            float acc = 0.f;
#pragma unroll
            for (int i = 0; i < 16; ++i) acc += xmv[i * 16 + x] * wr[i * 5 + GRADEA[x]];
            y[x] = acc;
        }
        float a0 = b_mv[o];
        const float* ws = w_s2mv + o * 32;
#pragma unroll
        for (int s = 0; s < 32; ++s) a0 += xs[s] * ws[s];
        y[0] += a0;
        const int head = o & 7, hid = o >> 3;
        float* op = out + ((size_t)(b * 8 + head) * ntok + n) * D_ + hid * 16;
#pragma unroll
        for (int x = 0; x < 16; ++x) op[x] = applyMetric ? y[x] * METRICA[x] : y[x];
    }
#pragma unroll
    for (int rr = 0; rr < 2; ++rr) {
        const int o = tid * 2 + rr;
        float y = b_s[o];
        const float* wm = w_mvs2s + o * 16;
#pragma unroll
        for (int i = 0; i < 16; ++i) y += xmv[i * 16] * wm[i];
        const float* ws = w_s2s + o * 32;
#pragma unroll
        for (int s = 0; s < 32; ++s) y += xs[s] * ws[s];
        const int head = o & 7, hid = o >> 3;
        out[((size_t)(b * 8 + head) * ntok + n) * D_ + 256 + hid] = y;
    }
}

// ============================================================================
// V transpose: VB [bh][n][288] -> VT [bh][288][n]
// ============================================================================
__global__ void transposeV_kernel()
{
    __shared__ float ts[32][33];
    const int bh = blockIdx.z, n0 = blockIdx.x * 32, d0 = blockIdx.y * 32;
    const int tid = threadIdx.x;
    const float* src = VB + ((size_t)bh * NKV_ + n0) * D_ + d0;
    float* dst = VT + ((size_t)bh * D_ + d0) * NKV_ + n0;
#pragma unroll
    for (int i = 0; i < 4; ++i) {
        int idx = i * 256 + tid, n = idx >> 5, dl = idx & 31;
        ts[n][dl] = src[(size_t)n * D_ + dl];
    }
    __syncthreads();
#pragma unroll
    for (int i = 0; i < 4; ++i) {
        int idx = i * 256 + tid, d = idx >> 5, nl = idx & 31;
        dst[(size_t)d * NKV_ + nl] = ts[nl][d];
    }
}

// ============================================================================
// Flash attention, tf32 mma.sync. grid=(16, 32), block=256.
// ============================================================================
#define QSTR 292
#define PSTR 68
#define KSTR 100
#define VSTR 68
#define QS_OFF 0
#define PS_OFF 18688
#define KV_OFF 23040
#define RED_OFF 29568
#define MR_OFF 29824
#define LR_OFF 29888
#define AR_OFF 29952
#define SMF 30016

__global__ __launch_bounds__(256, 1) void attn2_kernel()
{
    extern __shared__ float sm[];
    float* Qs = sm + QS_OFF;
    float* Ps = sm + PS_OFF;
    float* KV = sm + KV_OFF;
    float* red = sm + RED_OFF;
    float* mrow = sm + MR_OFF;
    float* lrow = sm + LR_OFF;
    float* arow = sm + AR_OFF;

    const int tid = threadIdx.x, bh = blockIdx.y, qt0 = blockIdx.x * 64;
    const int w = tid >> 5, lane = tid & 31, g = lane >> 2, t = lane & 3;
    const int wq = w & 1, wk = w >> 1;      // scores: q-slab(32), k-slab(16)
    const int wd = wk;                       // PV: d-quarter(24 per 96-chunk)
    const int r = tid >> 2, seg = tid & 3;   // softmax: 4 threads per row
    const float SCALE = 0.0589255650988789f; // 1/sqrt(288)

    const float* Qp  = QB + ((size_t)bh * NQ_ + qt0) * D_;
    const float* Kp  = KB + (size_t)bh * NKV_ * D_;
    const float* Vtp = VT + (size_t)bh * D_ * NKV_;

#pragma unroll
    for (int i = 0; i < 18; ++i) {
        int idx = i * 256 + tid, q = idx / 72, d4 = idx % 72;
        float4 v = *(const float4*)(Qp + (size_t)q * D_ + d4 * 4);
        float* dst = Qs + q * QSTR + d4 * 4;
        dst[0] = tf32f(v.x); dst[1] = tf32f(v.y); dst[2] = tf32f(v.z); dst[3] = tf32f(v.w);
    }
    if (tid < 64) { mrow[tid] = -1e30f; lrow[tid] = 0.f; }

    float O[3][3][2][4];
#pragma unroll
    for (int c = 0; c < 3; ++c)
#pragma unroll
        for (int nt = 0; nt < 3; ++nt)
#pragma unroll
            for (int mt = 0; mt < 2; ++mt)
#pragma unroll
                for (int j = 0; j < 4; ++j) O[c][nt][mt][j] = 0.f;

    for (int kt = 0; kt < NKV_ / 64; ++kt) {
        float cS[2][2][4];
#pragma unroll
        for (int mt = 0; mt < 2; ++mt)
#pragma unroll
            for (int nt = 0; nt < 2; ++nt)
#pragma unroll
                for (int j = 0; j < 4; ++j) cS[mt][nt][j] = 0.f;

        // ---- scores: 3 d-chunks of 96 ----
        for (int c = 0; c < 3; ++c) {
            __syncthreads();
            const float* kg = Kp + (size_t)(kt * 64) * D_ + c * 96;
#pragma unroll
            for (int i = 0; i < 6; ++i) {
                int idx = i * 256 + tid, key = idx / 24, d4 = idx % 24;
                float4 v = *(const float4*)(kg + (size_t)key * D_ + d4 * 4);
                float* dst = KV + key * KSTR + d4 * 4;
                dst[0] = tf32f(v.x); dst[1] = tf32f(v.y); dst[2] = tf32f(v.z); dst[3] = tf32f(v.w);
            }
            __syncthreads();
            const float* Qc = Qs + c * 96;
#pragma unroll
            for (int ds = 0; ds < 12; ++ds) {
                const float* qa = Qc + (wq * 32 + g) * QSTR + ds * 8 + t;
                uint32_t a00 = __float_as_uint(qa[0]);
                uint32_t a01 = __float_as_uint(qa[8 * QSTR]);
                uint32_t a02 = __float_as_uint(qa[4]);
                uint32_t a03 = __float_as_uint(qa[8 * QSTR + 4]);
                uint32_t a10 = __float_as_uint(qa[16 * QSTR]);
                uint32_t a11 = __float_as_uint(qa[24 * QSTR]);
                uint32_t a12 = __float_as_uint(qa[16 * QSTR + 4]);
                uint32_t a13 = __float_as_uint(qa[24 * QSTR + 4]);
                const float* kb = KV + (wk * 16 + g) * KSTR + ds * 8 + t;
                uint32_t b00 = __float_as_uint(kb[0]);
                uint32_t b01 = __float_as_uint(kb[4]);
                uint32_t b10 = __float_as_uint(kb[8 * KSTR]);
                uint32_t b11 = __float_as_uint(kb[8 * KSTR + 4]);
                MMA(cS[0][0], a00, a01, a02, a03, b00, b01);
                MMA(cS[0][1], a00, a01, a02, a03, b10, b11);
                MMA(cS[1][0], a10, a11, a12, a13, b00, b01);
                MMA(cS[1][1], a10, a11, a12, a13, b10, b11);
            }
        }
        // ---- frags -> Ps (raw scores) ----
#pragma unroll
        for (int mt = 0; mt < 2; ++mt)
#pragma unroll
            for (int nt = 0; nt < 2; ++nt) {
                int r0 = wq * 32 + 16 * mt + g, col = wk * 16 + nt * 8 + 2 * t;
                Ps[r0 * PSTR + col]           = cS[mt][nt][0];
                Ps[r0 * PSTR + col + 1]       = cS[mt][nt][1];
                Ps[(r0 + 8) * PSTR + col]     = cS[mt][nt][2];
                Ps[(r0 + 8) * PSTR + col + 1] = cS[mt][nt][3];
            }
        __syncthreads();

        // ---- online softmax ----
        {
            float lm = -1e30f;
            const float* pr = Ps + r * PSTR + seg * 16;
#pragma unroll
            for (int j = 0; j < 16; ++j) lm = fmaxf(lm, pr[j]);
            red[tid] = lm;
            __syncthreads();
            if (seg == 0) {
                float m4 = fmaxf(fmaxf(red[4 * r], red[4 * r + 1]),
                                 fmaxf(red[4 * r + 2], red[4 * r + 3])) * SCALE;
                float mo = mrow[r], mn = fmaxf(mo, m4);
                mrow[r] = mn; arow[r] = __expf(mo - mn);
            }
            __syncthreads();
            float mn = mrow[r], s = 0.f;
            float* pw = Ps + r * PSTR + seg * 16;
#pragma unroll
            for (int j = 0; j < 16; ++j) {
                float p = __expf(pw[j] * SCALE - mn);
                pw[j] = tf32f(p); s += p;
            }
            red[tid] = s;
            __syncthreads();
            if (seg == 0)
                lrow[r] = lrow[r] * arow[r] + red[4 * r] + red[4 * r + 1] + red[4 * r + 2] + red[4 * r + 3];
        }

        // ---- rescale O ----
        {
            float al0 = arow[wq * 32 + g],      al1 = arow[wq * 32 + 8 + g];
            float al2 = arow[wq * 32 + 16 + g], al3 = arow[wq * 32 + 24 + g];
#pragma unroll
            for (int c = 0; c < 3; ++c)
#pragma unroll
                for (int nt = 0; nt < 3; ++nt) {
                    O[c][nt][0][0] *= al0; O[c][nt][0][1] *= al0;
                    O[c][nt][0][2] *= al1; O[c][nt][0][3] *= al1;
                    O[c][nt][1][0] *= al2; O[c][nt][1][1] *= al2;
                    O[c][nt][1][2] *= al3; O[c][nt][1][3] *= al3;
                }
        }

        // ---- PV: 3 d-chunks ----
        for (int c = 0; c < 3; ++c) {
            __syncthreads();
            const float* vgp = Vtp + (size_t)(c * 96) * NKV_ + kt * 64;
#pragma unroll
            for (int i = 0; i < 6; ++i) {
                int idx = i * 256 + tid, j = idx / 16, k4 = idx % 16;
                float4 v = *(const float4*)(vgp + (size_t)j * NKV_ + k4 * 4);
                float* dst = KV + j * VSTR + k4 * 4;
                dst[0] = tf32f(v.x); dst[1] = tf32f(v.y); dst[2] = tf32f(v.z); dst[3] = tf32f(v.w);
            }
            __syncthreads();
#pragma unroll
            for (int ks = 0; ks < 8; ++ks) {
                const float* pa = Ps + (wq * 32 + g) * PSTR + ks * 8 + t;
                uint32_t a00 = __float_as_uint(pa[0]);
                uint32_t a01 = __float_as_uint(pa[8 * PSTR]);
                uint32_t a02 = __float_as_uint(pa[4]);
                uint32_t a03 = __float_as_uint(pa[8 * PSTR + 4]);
                uint32_t a10 = __float_as_uint(pa[16 * PSTR]);
                uint32_t a11 = __float_as_uint(pa[24 * PSTR]);
                uint32_t a12 = __float_as_uint(pa[16 * PSTR + 4]);
                uint32_t a13 = __float_as_uint(pa[24 * PSTR + 4]);
                const float* vb = KV + (wd * 24 + g) * VSTR + ks * 8 + t;
#pragma unroll
                for (int nt = 0; nt < 3; ++nt) {
                    uint32_t b0 = __float_as_uint(vb[nt * 8 * VSTR]);
                    uint32_t b1 = __float_as_uint(vb[nt * 8 * VSTR + 4]);
                    MMA(O[c][nt][0], a00, a01, a02, a03, b0, b1);
                    MMA(O[c][nt][1], a10, a11, a12, a13, b0, b1);
                }
            }
        }
    }

    __syncthreads();
    const float li0 = 1.f / lrow[wq * 32 + g],      li1 = 1.f / lrow[wq * 32 + 8 + g];
    const float li2 = 1.f / lrow[wq * 32 + 16 + g], li3 = 1.f / lrow[wq * 32 + 24 + g];
    const int b = bh >> 3, h = bh & 7;
#pragma unroll
    for (int c = 0; c < 3; ++c)
#pragma unroll
        for (int nt = 0; nt < 3; ++nt)
#pragma unroll
            for (int mt = 0; mt < 2; ++mt) {
                int r0 = wq * 32 + 16 * mt + g;
                int dcol = c * 96 + wd * 24 + nt * 8 + 2 * t;
                float lA = mt ? li2 : li0, lB = mt ? li3 : li1;
                size_t o0 = (((size_t)(b * NQ_ + qt0 + r0)) * 8 + h) * D_ + dcol;
                size_t o1 = (((size_t)(b * NQ_ + qt0 + r0 + 8)) * 8 + h) * D_ + dcol;
                float2 v0 = {O[c][nt][mt][0] * lA, O[c][nt][mt][1] * lA};
                float2 v1 = {O[c][nt][mt][2] * lB, O[c][nt][mt][3] * lB};
                *(float2*)(OB + o0) = v0;
                *(float2*)(OB + o1) = v1;
            }
}

// ============================================================================
// Output projection (one token per block, 256 threads) — unchanged from R0.
// ============================================================================
__global__ void outproj_kernel(const float* __restrict__ wo_mv, const float* __restrict__ wo_s2mv,
                               const float* __restrict__ wo_mvs2s, const float* __restrict__ wo_s2s,
                               const float* __restrict__ bo_mv, const float* __restrict__ bo_s,
                               float* __restrict__ d_out)
{
    __shared__ float xm[2048];
    __shared__ float xsc[256];
    const int t = blockIdx.x, tid = threadIdx.x;
    const float* ob = OB + (size_t)t * 8 * D_;

    for (int idx = tid; idx < 2048; idx += 256) {
        const int c = idx >> 4, x = idx & 15, head = c >> 4, hid = c & 15;
        xm[idx] = ob[head * D_ + hid * 16 + x];
    }
    {
        const int head = tid >> 5, hid = tid & 31;
        xsc[tid] = ob[head * D_ + 256 + hid];
    }
    __syncthreads();
    {
        const int o = tid >> 4, x = tid & 15, gg = GRADE_RT[x];
        const float* wmx = wo_mv + (size_t)o * 128 * 5 + gg;
        float y = 0.f;
#pragma unroll 8
        for (int i = 0; i < 128; ++i) y += xm[i * 16 + x] * wmx[i * 5];
        if (x == 0) {
            float a = bo_mv[o];
            const float* ws = wo_s2mv + o * 256;
#pragma unroll 8
            for (int s = 0; s < 256; ++s) a += xsc[s] * ws[s];
            y += a;
        }
        d_out[(size_t)t * 256 + o * 16 + x] = y;
    }
    if (tid < 32) {
        const int o = tid;
        float y = bo_s[o];
        const float* wm = wo_mvs2s + o * 128;
#pragma unroll 8
        for (int i = 0; i < 128; ++i) y += xm[i * 16] * wm[i];
        const float* ws = wo_s2s + o * 256;
#pragma unroll 8
        for (int s = 0; s < 256; ++s) y += xsc[s] * ws[s];
        d_out[(size_t)B_ * NQ_ * 256 + (size_t)t * 32 + o] = y;
    }
}

extern "C" void kernel_launch(void* const* d_in, const int* in_sizes, int n_in,
                              void* d_out, int out_size)
{
    (void)in_sizes; (void)n_in; (void)out_size;
    const float* mv_kv = (const float*)d_in[0];
    const float* mv_q  = (const float*)d_in[1];
    const float* s_kv  = (const float*)d_in[2];
    const float* s_q   = (const float*)d_in[3];
    const float* wq_mv = (const float*)d_in[4],  *wq_s2mv = (const float*)d_in[5];
    const float* wq_m2s = (const float*)d_in[6], *wq_s2s = (const float*)d_in[7];
    const float* bq_mv = (const float*)d_in[8],  *bq_s = (const float*)d_in[9];
    const float* wk_mv = (const float*)d_in[10], *wk_s2mv = (const float*)d_in[11];
    const float* wk_m2s = (const float*)d_in[12],*wk_s2s = (const float*)d_in[13];
    const float* bk_mv = (const float*)d_in[14], *bk_s = (const float*)d_in[15];
    const float* wv_mv = (const float*)d_in[16], *wv_s2mv = (const float*)d_in[17];
    const float* wv_m2s = (const float*)d_in[18],*wv_s2s = (const float*)d_in[19];
    const float* bv_mv = (const float*)d_in[20], *bv_s = (const float*)d_in[21];
    const float* wo_mv = (const float*)d_in[22], *wo_s2mv = (const float*)d_in[23];
    const float* wo_m2s = (const float*)d_in[24],*wo_s2s = (const float*)d_in[25];
    const float* bo_mv = (const float*)d_in[26], *bo_s = (const float*)d_in[27];

    const size_t attn_smem = SMF * sizeof(float);
    cudaFuncSetAttribute(attn2_kernel, cudaFuncAttributeMaxDynamicSharedMemorySize, (int)attn_smem);

    proj_kernel<<<B_ * NQ_, 128>>>(mv_q, s_q, wq_mv, wq_s2mv, wq_m2s, wq_s2s, bq_mv, bq_s, NQ_, 0, 0);
    proj_kernel<<<B_ * NKV_, 128>>>(mv_kv, s_kv, wk_mv, wk_s2mv, wk_m2s, wk_s2s, bk_mv, bk_s, NKV_, 1, 1);
    proj_kernel<<<B_ * NKV_, 128>>>(mv_kv, s_kv, wv_mv, wv_s2mv, wv_m2s, wv_s2s, bv_mv, bv_s, NKV_, 2, 0);
    transposeV_kernel<<<dim3(NKV_ / 32, D_ / 32, 32), 256>>>();
    attn2_kernel<<<dim3(NQ_ / 64, 32), 256, attn_smem>>>();
    outproj_kernel<<<B_ * NQ_, 256>>>(wo_mv, wo_s2mv, wo_m2s, wo_s2s, bo_mv, bo_s, (float*)d_out);
}

// round 4
// speedup vs baseline: 2.6118x; 1.1358x over previous
#include <cuda_runtime.h>
#include <math.h>
#include <stdint.h>

#define B_    4
#define NQ_   1024
#define NKV_  2048
#define D_    288

__device__ constexpr int   GRADEA[16] = {0,1,1,1,1,2,2,2,2,2,2,3,3,3,3,4};
__device__ constexpr float METRICA[16] = {1.f,1.f,-1.f,-1.f,-1.f,-1.f,-1.f,-1.f,
                                          1.f,1.f, 1.f, 1.f, 1.f, 1.f,-1.f,-1.f};
__constant__ int GRADE_RT[16] = {0,1,1,1,1,2,2,2,2,2,2,3,3,3,3,4};

// scratch (device globals)
__device__ float QB[(size_t)B_*8*NQ_*D_];
__device__ float KB[(size_t)B_*8*NKV_*D_];
__device__ float VB[(size_t)B_*8*NKV_*D_];
__device__ float OB[(size_t)B_*NQ_*8*D_];
// fragment-major operand buffers
__device__ float QF[(size_t)32*16*18432];   // [bh][qtile][mslab4][ds36][lane32][4]
__device__ float KF[(size_t)32*32*18432];   // [bh][ktile][half2][nslab8][dsl18][lane32][2]
__device__ float VF[(size_t)32*32*18432];   // [bh][ktile][half2][ks8][ntl18][lane32][2]

__device__ __forceinline__ float tf32f(float x) {
    uint32_t r; asm("cvt.rna.tf32.f32 %0,%1;" : "=r"(r) : "f"(x));
    return __uint_as_float(r);
}
#define MMA(c,a0,a1,a2,a3,b0,b1) \
    asm volatile("mma.sync.aligned.m16n8k8.row.col.f32.tf32.tf32.f32 " \
        "{%0,%1,%2,%3},{%4,%5,%6,%7},{%8,%9},{%0,%1,%2,%3};" \
        : "+f"((c)[0]),"+f"((c)[1]),"+f"((c)[2]),"+f"((c)[3]) \
        : "r"(a0),"r"(a1),"r"(a2),"r"(a3),"r"(b0),"r"(b1))

__device__ __forceinline__ void cp16(uint32_t dst, const float* src) {
    asm volatile("cp.async.ca.shared.global [%0],[%1],16;" :: "r"(dst), "l"(src));
}
#define CPCOMMIT() asm volatile("cp.async.commit_group;")
#define CPWAIT0()  asm volatile("cp.async.wait_group 0;")

// ============================================================================
// QKV projection (one token per block, 128 threads) — unchanged.
// ============================================================================
__global__ void proj_kernel(const float* __restrict__ x_mv, const float* __restrict__ x_s,
                            const float* __restrict__ w_mv, const float* __restrict__ w_s2mv,
                            const float* __restrict__ w_mvs2s, const float* __restrict__ w_s2s,
                            const float* __restrict__ b_mv, const float* __restrict__ b_s,
                            int ntok, int dst, int applyMetric)
{
    __shared__ float xmv[256];
    __shared__ float xs[32];
    const int t = blockIdx.x, b = t / ntok, n = t % ntok, tid = threadIdx.x;

    const float* xp = x_mv + (size_t)t * 256;
    xmv[tid] = xp[tid]; xmv[tid + 128] = xp[tid + 128];
    if (tid < 32) xs[tid] = x_s[(size_t)t * 32 + tid];
    __syncthreads();

    float* out = (dst == 0) ? QB : (dst == 1) ? KB : VB;
    {
        const int o = tid;
        const float* wr = w_mv + o * 80;
        float y[16];
#pragma unroll
        for (int x = 0; x < 16; ++x) {
            float acc = 0.f;
#pragma unroll
            for (int i = 0; i < 16; ++i) acc += xmv[i * 16 + x] * wr[i * 5 + GRADEA[x]];
            y[x] = acc;
        }
        float a0 = b_mv[o];
        const float* ws = w_s2mv + o * 32;
#pragma unroll
        for (int s = 0; s < 32; ++s) a0 += xs[s] * ws[s];
        y[0] += a0;
        const int head = o & 7, hid = o >> 3;
        float* op = out + ((size_t)(b * 8 + head) * ntok + n) * D_ + hid * 16;
#pragma unroll
        for (int x = 0; x < 16; ++x) op[x] = applyMetric ? y[x] * METRICA[x] : y[x];
    }
#pragma unroll
    for (int rr = 0; rr < 2; ++rr) {
        const int o = tid * 2 + rr;
        float y = b_s[o];
        const float* wm = w_mvs2s + o * 16;
#pragma unroll
        for (int i = 0; i < 16; ++i) y += xmv[i * 16] * wm[i];
        const float* ws = w_s2s + o * 32;
#pragma unroll
        for (int s = 0; s < 32; ++s) y += xs[s] * ws[s];
        const int head = o & 7, hid = o >> 3;
        out[((size_t)(b * 8 + head) * ntok + n) * D_ + 256 + hid] = y;
    }
}

// ============================================================================
// Repack kernels: stage a 64x288 tile in smem, emit fragment-major global.
// A-frag (m16n8k8): a0=(g,t) a1=(g+8,t) a2=(g,t+4) a3=(g+8,t+4)
// B-frag: b0=(k=t,n=g) b1=(k=t+4,n=g)
// ============================================================================
#define STG_STRIDE 292
__global__ void repackQ_kernel()
{
    extern __shared__ float ss[];
    const int qt = blockIdx.x, bh = blockIdx.y, tid = threadIdx.x;
    const float SCALE = 0.0589255650988789f;  // 1/sqrt(288), folded into Q
    const float* src = QB + ((size_t)bh * NQ_ + qt * 64) * D_;
#pragma unroll
    for (int i = 0; i < 18; ++i) {
        int idx = i * 256 + tid, row = idx / 72, c4 = idx % 72;
        float4 v = *(const float4*)(src + (size_t)row * D_ + c4 * 4);
        float* d = ss + row * STG_STRIDE + c4 * 4;
        d[0] = v.x; d[1] = v.y; d[2] = v.z; d[3] = v.w;
    }
    __syncthreads();
    float* dst = QF + (size_t)(bh * 16 + qt) * 18432;
#pragma unroll
    for (int i = 0; i < 18; ++i) {
        int e = i * 256 + tid;
        int m = e / 1152, rem = e % 1152, ds = rem >> 5, lane = rem & 31;
        int g = lane >> 2, t = lane & 3;
        int r0 = m * 16 + g, c0 = ds * 8 + t;
        float4 v;
        v.x = tf32f(ss[r0 * STG_STRIDE + c0] * SCALE);
        v.y = tf32f(ss[(r0 + 8) * STG_STRIDE + c0] * SCALE);
        v.z = tf32f(ss[r0 * STG_STRIDE + c0 + 4] * SCALE);
        v.w = tf32f(ss[(r0 + 8) * STG_STRIDE + c0 + 4] * SCALE);
        *(float4*)(dst + (size_t)e * 4) = v;
    }
}

__global__ void repackK_kernel()
{
    extern __shared__ float ss[];
    const int kt = blockIdx.x, bh = blockIdx.y, tid = threadIdx.x;
    const float* src = KB + ((size_t)bh * NKV_ + kt * 64) * D_;
#pragma unroll
    for (int i = 0; i < 18; ++i) {
        int idx = i * 256 + tid, row = idx / 72, c4 = idx % 72;
        float4 v = *(const float4*)(src + (size_t)row * D_ + c4 * 4);
        float* d = ss + row * STG_STRIDE + c4 * 4;
        d[0] = v.x; d[1] = v.y; d[2] = v.z; d[3] = v.w;
    }
    __syncthreads();
    float* dst = KF + (size_t)(bh * 32 + kt) * 18432;
#pragma unroll
    for (int i = 0; i < 36; ++i) {
        int e = i * 256 + tid;
        int lane = e & 31, tmp = e >> 5;
        int dsl = tmp % 18; tmp /= 18;
        int n = tmp & 7, half = tmp >> 3;
        int g = lane >> 2, t = lane & 3;
        int row = n * 8 + g, col = (half * 18 + dsl) * 8 + t;
        float2 v = { tf32f(ss[row * STG_STRIDE + col]),
                     tf32f(ss[row * STG_STRIDE + col + 4]) };
        *(float2*)(dst + (size_t)e * 2) = v;
    }
}

__global__ void repackV_kernel()
{
    extern __shared__ float ss[];
    const int kt = blockIdx.x, bh = blockIdx.y, tid = threadIdx.x;
    const float* src = VB + ((size_t)bh * NKV_ + kt * 64) * D_;
#pragma unroll
    for (int i = 0; i < 18; ++i) {
        int idx = i * 256 + tid, row = idx / 72, c4 = idx % 72;
        float4 v = *(const float4*)(src + (size_t)row * D_ + c4 * 4);
        float* d = ss + row * STG_STRIDE + c4 * 4;
        d[0] = v.x; d[1] = v.y; d[2] = v.z; d[3] = v.w;
    }
    __syncthreads();
    float* dst = VF + (size_t)(bh * 32 + kt) * 18432;
#pragma unroll
    for (int i = 0; i < 36; ++i) {
        int e = i * 256 + tid;
        int lane = e & 31, tmp = e >> 5;
        int ntl = tmp % 18; tmp /= 18;
        int ks = tmp & 7, half = tmp >> 3;
        int g = lane >> 2, t = lane & 3;
        int col = half * 144 + ntl * 8 + g, row0 = ks * 8 + t;
        float2 v = { tf32f(ss[row0 * STG_STRIDE + col]),
                     tf32f(ss[(row0 + 4) * STG_STRIDE + col]) };
        *(float2*)(dst + (size_t)e * 2) = v;
    }
}

// ============================================================================
// Flash attention: frag-major operands, cp.async ping-pong.
// grid=(16,32), block=256 (8 warps).
// ============================================================================
#define QS_OFF  0
#define BUFA_OFF 18432
#define BUFB_OFF 27648
#define PS_OFF  36864
#define RED_OFF 41216
#define MR_OFF  41472
#define LR_OFF  41536
#define AR_OFF  41600
#define SMF     41664
#define PSTR 68

__device__ __forceinline__ void ldtile(float* smbuf, const float* gsrc, int tid)
{
    uint32_t s0 = (uint32_t)__cvta_generic_to_shared(smbuf);
#pragma unroll
    for (int i = 0; i < 9; ++i) {
        int o = (i * 256 + tid) * 4;
        cp16(s0 + o * 4, gsrc + o);
    }
}

__device__ __forceinline__ void scores_half(const float* Qs, const float* buf,
                                            float cS[2][2][4], int h, int wqS, int wkS, int lane)
{
#pragma unroll
    for (int dsl = 0; dsl < 18; ++dsl) {
        const int ds = h * 18 + dsl;
        float4 A0 = *(const float4*)(Qs + (((2 * wqS) * 36 + ds) * 32 + lane) * 4);
        float4 A1 = *(const float4*)(Qs + (((2 * wqS + 1) * 36 + ds) * 32 + lane) * 4);
        float2 Bv0 = *(const float2*)(buf + (((2 * wkS) * 18 + dsl) * 32 + lane) * 2);
        float2 Bv1 = *(const float2*)(buf + (((2 * wkS + 1) * 18 + dsl) * 32 + lane) * 2);
        uint32_t a0 = __float_as_uint(A0.x), a1 = __float_as_uint(A0.y),
                 a2 = __float_as_uint(A0.z), a3 = __float_as_uint(A0.w);
        uint32_t c0 = __float_as_uint(A1.x), c1 = __float_as_uint(A1.y),
                 c2 = __float_as_uint(A1.z), c3 = __float_as_uint(A1.w);
        uint32_t b00 = __float_as_uint(Bv0.x), b01 = __float_as_uint(Bv0.y);
        uint32_t b10 = __float_as_uint(Bv1.x), b11 = __float_as_uint(Bv1.y);
        MMA(cS[0][0], a0, a1, a2, a3, b00, b01);
        MMA(cS[0][1], a0, a1, a2, a3, b10, b11);
        MMA(cS[1][0], c0, c1, c2, c3, b00, b01);
        MMA(cS[1][1], c0, c1, c2, c3, b10, b11);
    }
}

__device__ __forceinline__ void pv_half(const float* Ps, const float* buf,
                                        float O[2][9][4], int h, int wqP, int wdP,
                                        int g, int t, int lane)
{
#pragma unroll
    for (int ks = 0; ks < 8; ++ks) {
        const float* pb = Ps + (wqP * 16 + g) * PSTR + ks * 8 + t;
        uint32_t a0 = __float_as_uint(pb[0]);
        uint32_t a1 = __float_as_uint(pb[8 * PSTR]);
        uint32_t a2 = __float_as_uint(pb[4]);
        uint32_t a3 = __float_as_uint(pb[8 * PSTR + 4]);
#pragma unroll
        for (int ntl = 0; ntl < 9; ++ntl) {
            float2 Bv = *(const float2*)(buf + ((ks * 18 + wdP * 9 + ntl) * 32 + lane) * 2);
            MMA(O[h][ntl], a0, a1, a2, a3, __float_as_uint(Bv.x), __float_as_uint(Bv.y));
        }
    }
}

__global__ __launch_bounds__(256, 1) void attn3_kernel()
{
    extern __shared__ float sm[];
    float* Qs   = sm + QS_OFF;
    float* bufA = sm + BUFA_OFF;
    float* bufB = sm + BUFB_OFF;
    float* Ps   = sm + PS_OFF;
    float* red  = sm + RED_OFF;
    float* mrow = sm + MR_OFF;
    float* lrow = sm + LR_OFF;
    float* arow = sm + AR_OFF;

    const int tid = threadIdx.x, bh = blockIdx.y, qt = blockIdx.x;
    const int w = tid >> 5, lane = tid & 31, g = lane >> 2, t = lane & 3;
    const int wqS = w & 1, wkS = w >> 1;     // scores mapping
    const int wqP = w & 3, wdP = w >> 2;     // PV mapping
    const int r = tid >> 2, seg = tid & 3;   // softmax mapping

    const float* KFb = KF + (size_t)(bh * 32) * 18432;
    const float* VFb = VF + (size_t)(bh * 32) * 18432;

    // prefetch K(kt=0, half0) -> bufA
    ldtile(bufA, KFb, tid);
    CPCOMMIT();

    // load Q fragments (plain)
    {
        const float4* qsrc = (const float4*)(QF + (size_t)(bh * 16 + qt) * 18432);
        float4* qdst = (float4*)Qs;
#pragma unroll
        for (int i = 0; i < 18; ++i) qdst[i * 256 + tid] = qsrc[i * 256 + tid];
    }
    if (tid < 64) { mrow[tid] = -1e30f; lrow[tid] = 0.f; }

    float O[2][9][4];
#pragma unroll
    for (int h = 0; h < 2; ++h)
#pragma unroll
        for (int n = 0; n < 9; ++n)
#pragma unroll
            for (int j = 0; j < 4; ++j) O[h][n][j] = 0.f;

    for (int kt = 0; kt < 32; ++kt) {
        const float* KFt = KFb + (size_t)kt * 18432;
        const float* VFt = VFb + (size_t)kt * 18432;

        CPWAIT0(); __syncthreads();          // K half0 ready (+ Qs on first iter)
        ldtile(bufB, KFt + 9216, tid); CPCOMMIT();

        float cS[2][2][4];
#pragma unroll
        for (int mt = 0; mt < 2; ++mt)
#pragma unroll
            for (int nt = 0; nt < 2; ++nt)
#pragma unroll
                for (int j = 0; j < 4; ++j) cS[mt][nt][j] = 0.f;

        scores_half(Qs, bufA, cS, 0, wqS, wkS, lane);

        CPWAIT0(); __syncthreads();          // K half1 ready
        ldtile(bufA, VFt, tid); CPCOMMIT();
        scores_half(Qs, bufB, cS, 1, wqS, wkS, lane);

        // write raw scores
#pragma unroll
        for (int mt = 0; mt < 2; ++mt)
#pragma unroll
            for (int nt = 0; nt < 2; ++nt) {
                int row = wqS * 32 + mt * 16 + g, col = wkS * 16 + nt * 8 + 2 * t;
                *(float2*)(Ps + row * PSTR + col) = make_float2(cS[mt][nt][0], cS[mt][nt][1]);
                *(float2*)(Ps + (row + 8) * PSTR + col) = make_float2(cS[mt][nt][2], cS[mt][nt][3]);
            }
        __syncthreads();

        // softmax pass 1: row maxima
        {
            float lm = -1e30f;
            const float* pr = Ps + r * PSTR + seg * 16;
#pragma unroll
            for (int j = 0; j < 16; ++j) lm = fmaxf(lm, pr[j]);
            red[tid] = lm;
        }
        __syncthreads();
        if (tid < 64) {
            float m4 = fmaxf(fmaxf(red[4 * tid], red[4 * tid + 1]),
                             fmaxf(red[4 * tid + 2], red[4 * tid + 3]));
            float mo = mrow[tid], mn = fmaxf(mo, m4);
            mrow[tid] = mn; arow[tid] = __expf(mo - mn);
        }
        __syncthreads();
        // pass 2: exponentiate (tf32), partial sums
        {
            float mn = mrow[r], s = 0.f;
            float* pw = Ps + r * PSTR + seg * 16;
#pragma unroll
            for (int j = 0; j < 16; ++j) {
                float p = __expf(pw[j] - mn);
                pw[j] = tf32f(p); s += p;
            }
            red[tid] = s;
        }
        // rescale O (doesn't touch Ps/red of this pass)
        {
            float al0 = arow[wqP * 16 + g], al1 = arow[wqP * 16 + 8 + g];
#pragma unroll
            for (int h = 0; h < 2; ++h)
#pragma unroll
                for (int n = 0; n < 9; ++n) {
                    O[h][n][0] *= al0; O[h][n][1] *= al0;
                    O[h][n][2] *= al1; O[h][n][3] *= al1;
                }
        }
        CPWAIT0(); __syncthreads();          // V half0 ready + Ps/red visible
        if (tid < 64)
            lrow[tid] = lrow[tid] * arow[tid] +
                        red[4 * tid] + red[4 * tid + 1] + red[4 * tid + 2] + red[4 * tid + 3];

        ldtile(bufB, VFt + 9216, tid); CPCOMMIT();
        pv_half(Ps, bufA, O, 0, wqP, wdP, g, t, lane);

        CPWAIT0(); __syncthreads();          // V half1 ready
        if (kt < 31) { ldtile(bufA, KFt + 18432, tid); CPCOMMIT(); }
        pv_half(Ps, bufB, O, 1, wqP, wdP, g, t, lane);
    }

    __syncthreads();
    const float li0 = 1.f / lrow[wqP * 16 + g];
    const float li1 = 1.f / lrow[wqP * 16 + 8 + g];
    const int b = bh >> 3, hh = bh & 7;
    const int q0 = qt * 64 + wqP * 16 + g;
#pragma unroll
    for (int h = 0; h < 2; ++h)
#pragma unroll
        for (int n = 0; n < 9; ++n) {
            int d = h * 144 + (wdP * 9 + n) * 8 + 2 * t;
            size_t o0 = (((size_t)(b * NQ_ + q0)) * 8 + hh) * D_ + d;
            size_t o1 = (((size_t)(b * NQ_ + q0 + 8)) * 8 + hh) * D_ + d;
            *(float2*)(OB + o0) = make_float2(O[h][n][0] * li0, O[h][n][1] * li0);
            *(float2*)(OB + o1) = make_float2(O[h][n][2] * li1, O[h][n][3] * li1);
        }
}

// ============================================================================
// Output projection — unchanged.
// ============================================================================
__global__ void outproj_kernel(const float* __restrict__ wo_mv, const float* __restrict__ wo_s2mv,
                               const float* __restrict__ wo_mvs2s, const float* __restrict__ wo_s2s,
                               const float* __restrict__ bo_mv, const float* __restrict__ bo_s,
                               float* __restrict__ d_out)
{
    __shared__ float xm[2048];
    __shared__ float xsc[256];
    const int t = blockIdx.x, tid = threadIdx.x;
    const float* ob = OB + (size_t)t * 8 * D_;

    for (int idx = tid; idx < 2048; idx += 256) {
        const int c = idx >> 4, x = idx & 15, head = c >> 4, hid = c & 15;
        xm[idx] = ob[head * D_ + hid * 16 + x];
    }
    {
        const int head = tid >> 5, hid = tid & 31;
        xsc[tid] = ob[head * D_ + 256 + hid];
    }
    __syncthreads();
    {
        const int o = tid >> 4, x = tid & 15, gg = GRADE_RT[x];
        const float* wmx = wo_mv + (size_t)o * 128 * 5 + gg;
        float y = 0.f;
#pragma unroll 8
        for (int i = 0; i < 128; ++i) y += xm[i * 16 + x] * wmx[i * 5];
        if (x == 0) {
            float a = bo_mv[o];
            const float* ws = wo_s2mv + o * 256;
#pragma unroll 8
            for (int s = 0; s < 256; ++s) a += xsc[s] * ws[s];
            y += a;
        }
        d_out[(size_t)t * 256 + o * 16 + x] = y;
    }
    if (tid < 32) {
        const int o = tid;
        float y = bo_s[o];
        const float* wm = wo_mvs2s + o * 128;
#pragma unroll 8
        for (int i = 0; i < 128; ++i) y += xm[i * 16] * wm[i];
        const float* ws = wo_s2s + o * 256;
#pragma unroll 8
        for (int s = 0; s < 256; ++s) y += xsc[s] * ws[s];
        d_out[(size_t)B_ * NQ_ * 256 + (size_t)t * 32 + o] = y;
    }
}

extern "C" void kernel_launch(void* const* d_in, const int* in_sizes, int n_in,
                              void* d_out, int out_size)
{
    (void)in_sizes; (void)n_in; (void)out_size;
    const float* mv_kv = (const float*)d_in[0];
    const float* mv_q  = (const float*)d_in[1];
    const float* s_kv  = (const float*)d_in[2];
    const float* s_q   = (const float*)d_in[3];
    const float* wq_mv = (const float*)d_in[4],  *wq_s2mv = (const float*)d_in[5];
    const float* wq_m2s = (const float*)d_in[6], *wq_s2s = (const float*)d_in[7];
    const float* bq_mv = (const float*)d_in[8],  *bq_s = (const float*)d_in[9];
    const float* wk_mv = (const float*)d_in[10], *wk_s2mv = (const float*)d_in[11];
    const float* wk_m2s = (const float*)d_in[12],*wk_s2s = (const float*)d_in[13];
    const float* bk_mv = (const float*)d_in[14], *bk_s = (const float*)d_in[15];
    const float* wv_mv = (const float*)d_in[16], *wv_s2mv = (const float*)d_in[17];
    const float* wv_m2s = (const float*)d_in[18],*wv_s2s = (const float*)d_in[19];
    const float* bv_mv = (const float*)d_in[20], *bv_s = (const float*)d_in[21];
    const float* wo_mv = (const float*)d_in[22], *wo_s2mv = (const float*)d_in[23];
    const float* wo_m2s = (const float*)d_in[24],*wo_s2s = (const float*)d_in[25];
    const float* bo_mv = (const float*)d_in[26], *bo_s = (const float*)d_in[27];

    const int stage_smem = 64 * STG_STRIDE * sizeof(float);   // 74,752B
    cudaFuncSetAttribute(repackQ_kernel, cudaFuncAttributeMaxDynamicSharedMemorySize, stage_smem);
    cudaFuncSetAttribute(repackK_kernel, cudaFuncAttributeMaxDynamicSharedMemorySize, stage_smem);
    cudaFuncSetAttribute(repackV_kernel, cudaFuncAttributeMaxDynamicSharedMemorySize, stage_smem);
    const int attn_smem = SMF * sizeof(float);                // 166,656B
    cudaFuncSetAttribute(attn3_kernel, cudaFuncAttributeMaxDynamicSharedMemorySize, attn_smem);

    proj_kernel<<<B_ * NQ_, 128>>>(mv_q, s_q, wq_mv, wq_s2mv, wq_m2s, wq_s2s, bq_mv, bq_s, NQ_, 0, 0);
    proj_kernel<<<B_ * NKV_, 128>>>(mv_kv, s_kv, wk_mv, wk_s2mv, wk_m2s, wk_s2s, bk_mv, bk_s, NKV_, 1, 1);
    proj_kernel<<<B_ * NKV_, 128>>>(mv_kv, s_kv, wv_mv, wv_s2mv, wv_m2s, wv_s2s, bv_mv, bv_s, NKV_, 2, 0);

    repackQ_kernel<<<dim3(16, 32), 256, stage_smem>>>();
    repackK_kernel<<<dim3(32, 32), 256, stage_smem>>>();
    repackV_kernel<<<dim3(32, 32), 256, stage_smem>>>();

    attn3_kernel<<<dim3(16, 32), 256, attn_smem>>>();

    outproj_kernel<<<B_ * NQ_, 256>>>(wo_mv, wo_s2mv, wo_m2s, wo_s2s, bo_mv, bo_s, (float*)d_out);
}